// round 15
// baseline (speedup 1.0000x reference)
#include <cuda_runtime.h>
#include <math.h>

#define BB 8
#define NN 2048
#define FD 256
#define KK 205          // int(2048*0.1)+1
#define ACAP 320        // active-column capacity (expected ~205)
#define NNZCAP 256      // nnz-per-row capacity (expected ~41)
#define SCCAP 48        // active entries per Sc row (expected ~4)
#define NWORD 10        // ACAP/32 bitmask words

// ---- output layout (concatenated f32): x_c | coarse | S | topi ----
#define OFF_XC 0ULL
#define OFF_CO 4194304ULL                 // 8*2048*256
#define OFF_S  37748736ULL                // + 8*2048*2048
#define OFF_TI 71303168ULL                // + 8*2048*2048

// ---- device scratch ----
__device__ float    g_dg   [BB*NN];
__device__ float    g_mask [BB*NN];
__device__ float    g_y    [BB*NN];
__device__ float    g_alpha[BB*NN];
__device__ float    g_ca   [BB*NN];
__device__ int      g_cnt  [BB*NN];
__device__ int      g_need [BB*NN];
__device__ int      g_col  [(size_t)BB*NN*NNZCAP];
__device__ float    g_val  [(size_t)BB*NN*NNZCAP];
__device__ int      g_aidx [BB*ACAP];
__device__ int      g_acnt [BB];
__device__ int      g_cmap [BB*NN];
__device__ float    g_scvals[(size_t)BB*NN*SCCAP];   // compact Sc values (a-ascending)
__device__ int      g_scj  [(size_t)BB*NN*SCCAP];    // column index j per compact entry
__device__ int      g_scn  [BB*NN];                  // compact count per row
__device__ uint2    g_scmb [BB*NN*NWORD];            // (bitmask, popc-base) per word
__device__ float    g_Tt   [(size_t)BB*NN*ACAP];
__device__ float    g_cact [(size_t)BB*ACAP*ACAP];   // coarse active core [a][c]

// Sc[rown, a] lookup via bitmask + popc into compact values.
__device__ __forceinline__ float sc_lookup(int rown, int a) {
    uint2 mb = g_scmb[rown*NWORD + (a >> 5)];
    int bit = a & 31;
    if (!((mb.x >> bit) & 1u)) return 0.f;
    int pos = (int)mb.y + __popc(mb.x & ((1u << bit) - 1u));
    return g_scvals[(size_t)rown*SCCAP + pos];
}

// ---------------------------------------------------------------
// L1: fused head. blocks [0,16384): rowstats. blocks [16384,18432): raw y.
// ---------------------------------------------------------------
__global__ void k_head(const float* __restrict__ adj,
                       const float* __restrict__ x,
                       const float* __restrict__ W) {
    int t = threadIdx.x;               // 256
    int lane = t & 31, w = t >> 5;

    if (blockIdx.x >= BB * NN) {
        int row = (blockIdx.x - BB * NN) * 8 + w;
        const float* xr = x + (size_t)row * FD;
        float s = 0.f;
        #pragma unroll
        for (int f = lane; f < FD; f += 32) s += xr[f] * W[f];
        #pragma unroll
        for (int o = 16; o > 0; o >>= 1) s += __shfl_down_sync(0xffffffffu, s, o);
        if (lane == 0) g_y[row] = s;
        return;
    }

    int row = blockIdx.x;
    const float* ar = adj + (size_t)row * NN;

    float v[8];
    float4 u0 = __ldcs(((const float4*)ar) + t * 2);
    float4 u1 = __ldcs(((const float4*)ar) + t * 2 + 1);
    v[0]=u0.x; v[1]=u0.y; v[2]=u0.z; v[3]=u0.w;
    v[4]=u1.x; v[5]=u1.y; v[6]=u1.z; v[7]=u1.w;

    float s = 0.f; int c = 0; unsigned em = 0;
    #pragma unroll
    for (int i = 0; i < 8; i++) { s += v[i]; if (v[i] != 0.f) { c++; em |= 1u << i; } }

    int csc = c;
    #pragma unroll
    for (int o = 1; o < 32; o <<= 1) {
        int n = __shfl_up_sync(0xffffffffu, csc, o);
        if (lane >= o) csc += n;
    }
    float ss = s;
    #pragma unroll
    for (int o = 16; o > 0; o >>= 1) ss += __shfl_xor_sync(0xffffffffu, ss, o);

    __shared__ int   wtot[8];
    __shared__ float wsum[8];
    __shared__ int   wbase[9];
    __shared__ float s_rs;
    if (lane == 31) wtot[w] = csc;
    if (lane == 0)  wsum[w] = ss;
    __syncthreads();
    if (t == 0) {
        int acc = 0; float rs = 0.f;
        #pragma unroll
        for (int k = 0; k < 8; k++) { wbase[k] = acc; acc += wtot[k]; rs += wsum[k]; }
        wbase[8] = acc; s_rs = rs;
    }
    __syncthreads();

    int pos = wbase[w] + csc - c;
    size_t ob = (size_t)row * NNZCAP;
    int basecol = t * 8;
    #pragma unroll
    for (int i = 0; i < 8; i++) {
        if ((em >> i) & 1u) {
            if (pos < NNZCAP) { g_col[ob + pos] = basecol + i; g_val[ob + pos] = v[i]; }
            pos++;
        }
    }
    if (t == 0) {
        int total = wbase[8];
        float rs = s_rs;
        g_cnt[row]  = (total < NNZCAP) ? total : NNZCAP;
        g_dg[row]   = 1.f / sqrtf(rs + 1.f);
        g_mask[row] = (rs > 0.f) ? 1.f : 0.f;
        g_need[row] = 0;
    }
}

// L2: alpha[n] = sigmoid( (dg_n*(sum_nbr val*dg*y + dg_n*y_n) + b)^2 )
__global__ void k_alpha(const float* __restrict__ bptr) {
    int row  = blockIdx.x * 8 + (threadIdx.x >> 5);
    int lane = threadIdx.x & 31;
    int nb   = (row >> 11) << 11;
    int cnt  = g_cnt[row];
    size_t base = (size_t)row * NNZCAP;
    float z = 0.f;
    for (int e = lane; e < cnt; e += 32) {
        int nc = nb + g_col[base + e];
        z += g_val[base + e] * g_dg[nc] * g_y[nc];
    }
    #pragma unroll
    for (int o = 16; o > 0; o >>= 1) z += __shfl_down_sync(0xffffffffu, z, o);
    if (lane == 0) {
        float dgn = g_dg[row];
        float ap  = dgn * (z + dgn * g_y[row]) + bptr[0];
        float tt  = ap * ap;
        g_alpha[row] = 1.f / (1.f + expf(-tt));
    }
}

// block-wide inclusive scan, 1024 threads (32 warps). wsum: shared int[32].
__device__ __forceinline__ int bscan1024(int v, int lane, int w, int* wsum) {
    __syncthreads();
    int x = v;
    #pragma unroll
    for (int o = 1; o < 32; o <<= 1) {
        int n = __shfl_up_sync(0xffffffffu, x, o);
        if (lane >= o) x += n;
    }
    if (lane == 31) wsum[w] = x;
    __syncthreads();
    if (w == 0) {
        int s = wsum[lane];
        #pragma unroll
        for (int o = 1; o < 32; o <<= 1) {
            int n = __shfl_up_sync(0xffffffffu, s, o);
            if (lane >= o) s += n;
        }
        wsum[lane] = s;
    }
    __syncthreads();
    if (w > 0) x += wsum[w - 1];
    return x;
}

// L3: histogram radix-select + 512 bitonic (exact lax.top_k order),
// cut, topi, cut_alpha, active list/colmap, mark rows needed by T.
__global__ void k_topk(float* __restrict__ out, long long out_size) {
    int b = blockIdx.x;
    int t = threadIdx.x;  // 1024
    int lane = t & 31, w = t >> 5;
    int nb = b << 11;
    __shared__ int hist[1024];
    __shared__ int wsum[32];
    __shared__ unsigned long long cand[512];
    __shared__ int s_T, s_C, s_acnt;
    __shared__ float s_cut;

    hist[t] = 0;
    if (t == 0) s_C = 0;
    __syncthreads();

    unsigned b0 = __float_as_uint(g_alpha[nb + 2*t]);
    unsigned b1 = __float_as_uint(g_alpha[nb + 2*t + 1]);
    int bin0 = (int)(b0 >> 13) - 0x1F800; bin0 = bin0 < 0 ? 0 : (bin0 > 1023 ? 1023 : bin0);
    int bin1 = (int)(b1 >> 13) - 0x1F800; bin1 = bin1 < 0 ? 0 : (bin1 > 1023 ? 1023 : bin1);
    atomicAdd(&hist[bin0], 1);
    atomicAdd(&hist[bin1], 1);
    __syncthreads();

    int r = 1023 - t;
    int hv = hist[r];
    int sufi = bscan1024(hv, lane, w, wsum);
    int sufn = sufi - hv;
    if (sufi >= KK && sufn < KK) s_T = r;
    __syncthreads();
    int T = s_T;

    if (bin0 >= T) {
        int p = atomicAdd(&s_C, 1);
        if (p < 512) cand[p] = ((unsigned long long)(0xFFFFFFFFu - b0) << 32) | (unsigned)(2*t);
    }
    if (bin1 >= T) {
        int p = atomicAdd(&s_C, 1);
        if (p < 512) cand[p] = ((unsigned long long)(0xFFFFFFFFu - b1) << 32) | (unsigned)(2*t + 1);
    }
    __syncthreads();
    int C = s_C < 512 ? s_C : 512;
    if (t >= C && t < 512) cand[t] = 0xFFFFFFFFFFFFFFFFULL;
    __syncthreads();

    for (int sz = 2; sz <= 512; sz <<= 1) {
        for (int st = sz >> 1; st > 0; st >>= 1) {
            if (t < 512) {
                int p = t ^ st;
                if (p > t) {
                    bool up = ((t & sz) == 0);
                    unsigned long long a = cand[t], c2 = cand[p];
                    if ((a > c2) == up) { cand[t] = c2; cand[p] = a; }
                }
            }
            __syncthreads();
        }
    }

    if (t == 0) {
        unsigned vb = 0xFFFFFFFFu - (unsigned)(cand[KK - 1] >> 32);
        s_cut = __uint_as_float(vb);
    }
    if (t < KK) {
        int idx = (int)(cand[t] & 0xFFFFFFFFULL);
        long long o = (long long)OFF_TI + (long long)b * KK + t;
        if (o < out_size) out[o] = (float)idx;
    }
    __syncthreads();
    float cut = s_cut;

    int j0 = 2*t, j1 = 2*t + 1;
    float ca0 = fmaxf((__uint_as_float(b0) + 1e-7f) - cut, 0.f);
    float ca1 = fmaxf((__uint_as_float(b1) + 1e-7f) - cut, 0.f);
    g_ca[nb + j0] = ca0;
    g_ca[nb + j1] = ca1;
    int p0 = ca0 > 0.f ? 1 : 0, p1 = ca1 > 0.f ? 1 : 0;
    int incl = bscan1024(p0 + p1, lane, w, wsum);
    int excl = incl - (p0 + p1);
    if (p0) { int pos = excl;      if (pos < ACAP) { g_cmap[nb+j0] = pos; g_aidx[b*ACAP+pos] = j0; } else g_cmap[nb+j0] = -1; }
    else g_cmap[nb + j0] = -1;
    if (p1) { int pos = excl + p0; if (pos < ACAP) { g_cmap[nb+j1] = pos; g_aidx[b*ACAP+pos] = j1; } else g_cmap[nb+j1] = -1; }
    else g_cmap[nb + j1] = -1;
    if (t == 1023) s_acnt = (incl < ACAP) ? incl : ACAP;
    __syncthreads();
    int AC = s_acnt;
    if (t == 1023) g_acnt[b] = AC;

    for (int p = t; p < AC; p += 1024) {
        int j = g_aidx[b * ACAP + p];
        int rowj = nb + j;
        g_need[rowj] = 1;
        int c = g_cnt[rowj];
        size_t ba = (size_t)rowj * NNZCAP;
        for (int e = 0; e < c; e++) g_need[nb + g_col[ba + e]] = 1;
    }
}

// L4: block per row (256 thr): cooperative sparse-entry build, rowsum,
// compact Sc ONLY (vals + j-list + count + packed mask/base). No dense write.
__global__ void k_Sc() {
    __shared__ int   s_a[SCCAP];
    __shared__ int   s_j[SCCAP];
    __shared__ float s_v[SCCAP];
    __shared__ int   s_wi[8];
    __shared__ float s_wf[8];
    __shared__ int   s_diag, s_cntLess, s_tot, s_base[8];
    __shared__ float s_rowsum;
    __shared__ unsigned s_mw[NWORD];

    int row = blockIdx.x;
    int t = threadIdx.x, lane = t & 31, w = t >> 5;
    int b = row >> 11, i = row & 2047, nb = b << 11;
    int cnt = g_cnt[row];
    if (t == 0) s_diag = 0;

    bool valid = t < cnt;
    int j = 0, a = -1; float sval = 0.f;
    if (valid) {
        j = g_col[(size_t)row * NNZCAP + t];
        float val = g_val[(size_t)row * NNZCAP + t];
        int nc = nb + j;
        a = g_cmap[nc];
        if (a >= 0) sval = val * g_dg[nc] * g_ca[nc];
    }
    int   selfA   = g_cmap[row];
    float dgi     = g_dg[row];
    float selfVal = dgi * g_ca[row];
    bool act = valid && (a >= 0);
    __syncthreads();
    if (act && j == i) { sval += selfVal; s_diag = 1; }
    __syncthreads();
    bool selfIns = (selfA >= 0) && (s_diag == 0);

    float fv = act ? sval : 0.f;
    int   iv = (act && j < i) ? 1 : 0;
    #pragma unroll
    for (int o = 16; o > 0; o >>= 1) {
        fv += __shfl_xor_sync(0xffffffffu, fv, o);
        iv += __shfl_xor_sync(0xffffffffu, iv, o);
    }
    if (lane == 0) { s_wf[w] = fv; s_wi[w] = iv; }
    __syncthreads();
    if (t == 0) {
        float rs = 0.f; int cl = 0;
        #pragma unroll
        for (int k = 0; k < 8; k++) { rs += s_wf[k]; cl += s_wi[k]; }
        if (selfIns) rs += selfVal;
        s_rowsum = rs; s_cntLess = cl;
    }
    __syncthreads();

    int sc = act ? 1 : 0, x = sc;
    #pragma unroll
    for (int o = 1; o < 32; o <<= 1) {
        int n = __shfl_up_sync(0xffffffffu, x, o);
        if (lane >= o) x += n;
    }
    if (lane == 31) s_wi[w] = x;
    __syncthreads();
    if (t == 0) {
        int acc = 0;
        #pragma unroll
        for (int k = 0; k < 8; k++) { s_base[k] = acc; acc += s_wi[k]; }
        s_tot = acc;
    }
    __syncthreads();
    int rank = s_base[w] + (x - sc) + ((selfIns && j > i) ? 1 : 0);
    if (act && rank < SCCAP) { s_a[rank] = a; s_j[rank] = j; s_v[rank] = sval; }
    if (selfIns && t == 0) {
        int r2 = s_cntLess;
        if (r2 < SCCAP) { s_a[r2] = selfA; s_j[r2] = i; s_v[r2] = selfVal; }
    }
    __syncthreads();

    int ns = s_tot + (selfIns ? 1 : 0);
    if (ns > SCCAP) ns = SCCAP;
    float factor = g_mask[row] * dgi;
    float denom  = fmaxf(factor * s_rowsum, 1e-12f);
    float scale  = factor / denom;

    if (t < NWORD) {
        unsigned m = 0;
        for (int q = 0; q < ns; q++) if ((s_a[q] >> 5) == t) m |= 1u << (s_a[q] & 31);
        s_mw[t] = m;
    }
    __syncthreads();
    if (t < NWORD) {
        int bs = 0;
        for (int k = 0; k < t; k++) bs += __popc(s_mw[k]);
        g_scmb[row * NWORD + t] = make_uint2(s_mw[t], (unsigned)bs);
    }
    if (t < ns) {
        g_scvals[(size_t)row * SCCAP + t] = s_v[t] * scale;
        g_scj  [(size_t)row * SCCAP + t] = s_j[t];
    }
    if (t == 0) g_scn[row] = ns;
}

// L5 (320 thr): seg A [0, 2560): x_c active rows. seg B: Tt for needed rows.
__global__ void k_Txc(const float* __restrict__ x, float* __restrict__ out) {
    int t = threadIdx.x;   // 320
    unsigned bid = blockIdx.x;

    if (bid < BB * ACAP) {
        int b = bid / ACAP, a = bid % ACAP;
        int AC = g_acnt[b];
        if (a >= AC) return;
        int nb = b << 11;
        int m = g_aidx[b * ACAP + a];
        int row = nb + m;
        int cnt = g_cnt[row];
        size_t base = (size_t)row * NNZCAP;

        __shared__ float s_w[NNZCAP];
        __shared__ int   s_nr[NNZCAP];
        __shared__ int   s_diag;
        if (t == 0) s_diag = 0;
        __syncthreads();
        for (int e = t; e < cnt; e += 320) {
            int jj = g_col[base + e];
            int nr = nb + jj;
            s_nr[e] = nr;
            s_w[e] = sc_lookup(nr, a);
            if (jj == m) s_diag = 1;
        }
        __syncthreads();
        if (t < FD) {
            float acc = 0.f;
            for (int e = 0; e < cnt; e++) acc += s_w[e] * x[(size_t)s_nr[e] * FD + t];
            if (!s_diag) acc += sc_lookup(row, a) * x[(size_t)row * FD + t];
            out[OFF_XC + (size_t)row * FD + t] = acc;
        }
    } else {
        int row = bid - BB * ACAP;
        if (!g_need[row]) return;
        int b = row >> 11, nb = b << 11;
        int AC = g_acnt[b];
        int cnt = g_cnt[row];
        size_t base = (size_t)row * NNZCAP;
        int widx = t >> 5, lane = t & 31;
        unsigned ltm = (1u << lane) - 1u;

        __shared__ float s_v[32];
        __shared__ int   s_rn[32];
        __shared__ uint2 s_mb[32 * NWORD];

        float acc = 0.f;
        for (int c0 = 0; c0 < cnt; c0 += 32) {
            int nch = cnt - c0; if (nch > 32) nch = 32;
            __syncthreads();
            if (t < nch) {
                s_rn[t] = nb + g_col[base + c0 + t];
                s_v[t]  = g_val[base + c0 + t];
            }
            __syncthreads();
            {
                int e = t & 31, w2 = t >> 5;   // 320 = 32 x 10 exactly
                if (e < nch) s_mb[e * NWORD + w2] = g_scmb[s_rn[e] * NWORD + w2];
            }
            __syncthreads();
            for (int e = 0; e < nch; e++) {
                uint2 mb = s_mb[e * NWORD + widx];
                if ((mb.x >> lane) & 1u) {
                    int pos = (int)mb.y + __popc(mb.x & ltm);
                    acc += s_v[e] * g_scvals[(size_t)s_rn[e] * SCCAP + pos];
                }
            }
        }
        if (t < AC) g_Tt[(size_t)row * ACAP + t] = acc;
    }
}

// L6: coarse core: g_cact[a][c] = sum_{k in nbr(j_c) U {j_c}} Sc[k,c]*Tt[k,a]
__global__ void k_cact() {
    int b = blockIdx.x / ACAP, c = blockIdx.x % ACAP;
    int AC = g_acnt[b];
    if (c >= AC) return;
    int nb = b << 11;
    int j = g_aidx[b * ACAP + c];
    int rowj = nb + j;
    int cnt = g_cnt[rowj];
    size_t base = (size_t)rowj * NNZCAP;
    int t = threadIdx.x;  // 320

    __shared__ float s_w[NNZCAP];
    __shared__ int   s_kr[NNZCAP];
    __shared__ int   s_diag;
    if (t == 0) s_diag = 0;
    __syncthreads();
    for (int e = t; e < cnt; e += 320) {
        int k = g_col[base + e];
        int kr = nb + k;
        s_kr[e] = kr;
        s_w[e] = sc_lookup(kr, c);
        if (k == j) s_diag = 1;
    }
    __syncthreads();

    if (t < AC) {
        float acc = 0.f;
        for (int e = 0; e < cnt; e++) {
            float ww = s_w[e];
            if (ww != 0.f) acc += ww * g_Tt[(size_t)s_kr[e] * ACAP + t];
        }
        if (!s_diag) {
            float ww = sc_lookup(rowj, c);
            if (ww != 0.f) acc += ww * g_Tt[(size_t)rowj * ACAP + t];
        }
        g_cact[(size_t)b * ACAP * ACAP + (size_t)t * ACAP + c] = acc;
    }
}

// L7: pure output stream. blocks [0,16384): S rows (zero-fill + ns patches).
// blocks [16384,32768): coarse rows (zero-fill + AC quantized patches for
// active rows) + inactive-x_c zeros.
__global__ void k_final(float* __restrict__ out) {
    int t = threadIdx.x;   // 256
    unsigned bid = blockIdx.x;
    float4 z = make_float4(0.f, 0.f, 0.f, 0.f);

    if (bid < BB * NN) {
        int row = bid;
        float4* op = (float4*)(out + OFF_S + (size_t)row * NN);
        #pragma unroll 2
        for (int i = t; i < NN / 4; i += 256) __stcs(op + i, z);
        __syncthreads();
        int ns = g_scn[row];
        if (t < ns)
            out[OFF_S + (size_t)row * NN + g_scj[(size_t)row * SCCAP + t]] =
                g_scvals[(size_t)row * SCCAP + t];
    } else {
        int row = bid - BB * NN;
        int b = row >> 11;
        float4* co = (float4*)(out + OFF_CO + (size_t)row * NN);
        #pragma unroll 2
        for (int i = t; i < NN / 4; i += 256) __stcs(co + i, z);
        int a = g_cmap[row];
        if (a < 0) {
            if (t < FD / 4) __stcs((float4*)(out + OFF_XC + (size_t)row * FD) + t, z);
            return;
        }
        __syncthreads();
        int AC = g_acnt[b];
        const float* crow = g_cact + (size_t)b * ACAP * ACAP + (size_t)a * ACAP;
        const int* ai = g_aidx + b * ACAP;
        for (int c = t; c < AC; c += 256) {
            float q = floorf(crow[c] * 10000.0f) / 10000.0f;
            out[OFF_CO + (size_t)row * NN + ai[c]] = q;
        }
    }
}

extern "C" void kernel_launch(void* const* d_in, const int* in_sizes, int n_in,
                              void* d_out, int out_size) {
    const float* x    = (const float*)d_in[0];
    const float* adj  = (const float*)d_in[1];
    const float* W    = (const float*)d_in[2];
    const float* bptr = (const float*)d_in[3];
    float* out = (float*)d_out;

    k_head  <<<BB * NN + BB * NN / 8, 256>>>(adj, x, W);        // 1
    k_alpha <<<BB * NN / 8, 256>>>(bptr);                       // 2
    k_topk  <<<BB, 1024>>>(out, (long long)out_size);           // 3
    k_Sc    <<<BB * NN, 256>>>();                               // 4 (ncu slot)
    k_Txc   <<<BB * ACAP + BB * NN, 320>>>(x, out);             // 5
    k_cact  <<<BB * ACAP, 320>>>();                             // 6
    k_final <<<2 * BB * NN, 256>>>(out);                        // 7
}

// round 16
// speedup vs baseline: 1.1437x; 1.1437x over previous
#include <cuda_runtime.h>
#include <math.h>

#define BB 8
#define NN 2048
#define FD 256
#define KK 205          // int(2048*0.1)+1
#define ACAP 320        // active-column capacity (expected ~205)
#define NNZCAP 256      // nnz-per-row capacity (expected ~41)
#define SCCAP 48        // active entries per Sc row (expected ~4)
#define NWORD 10        // ACAP/32 bitmask words

// ---- output layout (concatenated f32): x_c | coarse | S | topi ----
#define OFF_XC 0ULL
#define OFF_CO 4194304ULL                 // 8*2048*256
#define OFF_S  37748736ULL                // + 8*2048*2048
#define OFF_TI 71303168ULL                // + 8*2048*2048

// ---- device scratch ----
__device__ float    g_dg   [BB*NN];
__device__ float    g_mask [BB*NN];
__device__ float    g_y    [BB*NN];
__device__ float    g_alpha[BB*NN];
__device__ float    g_ca   [BB*NN];
__device__ int      g_cnt  [BB*NN];
__device__ int      g_need [BB*NN];
__device__ int      g_col  [(size_t)BB*NN*NNZCAP];
__device__ float    g_val  [(size_t)BB*NN*NNZCAP];
__device__ int      g_aidx [BB*ACAP];
__device__ int      g_acnt [BB];
__device__ int      g_cmap [BB*NN];
__device__ float    g_scvals[(size_t)BB*NN*SCCAP];   // compact Sc values (a-ascending)
__device__ int      g_scj  [(size_t)BB*NN*SCCAP];    // column index j per compact entry
__device__ int      g_scn  [BB*NN];                  // compact count per row
__device__ uint2    g_scmb [BB*NN*NWORD];            // (bitmask, popc-base) per word
__device__ float    g_Tt   [(size_t)BB*NN*ACAP];
__device__ float    g_cact [(size_t)BB*ACAP*ACAP];   // coarse active core [a][c]

// Sc[rown, a] lookup via bitmask + popc into compact values.
__device__ __forceinline__ float sc_lookup(int rown, int a) {
    uint2 mb = g_scmb[rown*NWORD + (a >> 5)];
    int bit = a & 31;
    if (!((mb.x >> bit) & 1u)) return 0.f;
    int pos = (int)mb.y + __popc(mb.x & ((1u << bit) - 1u));
    return g_scvals[(size_t)rown*SCCAP + pos];
}

// ---------------------------------------------------------------
// L1: fused head. blocks [0,16384): rowstats. blocks [16384,18432): raw y.
// ---------------------------------------------------------------
__global__ void k_head(const float* __restrict__ adj,
                       const float* __restrict__ x,
                       const float* __restrict__ W) {
    int t = threadIdx.x;               // 256
    int lane = t & 31, w = t >> 5;

    if (blockIdx.x >= BB * NN) {
        int row = (blockIdx.x - BB * NN) * 8 + w;
        const float* xr = x + (size_t)row * FD;
        float s = 0.f;
        #pragma unroll
        for (int f = lane; f < FD; f += 32) s += xr[f] * W[f];
        #pragma unroll
        for (int o = 16; o > 0; o >>= 1) s += __shfl_down_sync(0xffffffffu, s, o);
        if (lane == 0) g_y[row] = s;
        return;
    }

    int row = blockIdx.x;
    const float* ar = adj + (size_t)row * NN;

    float v[8];
    float4 u0 = __ldcs(((const float4*)ar) + t * 2);
    float4 u1 = __ldcs(((const float4*)ar) + t * 2 + 1);
    v[0]=u0.x; v[1]=u0.y; v[2]=u0.z; v[3]=u0.w;
    v[4]=u1.x; v[5]=u1.y; v[6]=u1.z; v[7]=u1.w;

    float s = 0.f; int c = 0; unsigned em = 0;
    #pragma unroll
    for (int i = 0; i < 8; i++) { s += v[i]; if (v[i] != 0.f) { c++; em |= 1u << i; } }

    int csc = c;
    #pragma unroll
    for (int o = 1; o < 32; o <<= 1) {
        int n = __shfl_up_sync(0xffffffffu, csc, o);
        if (lane >= o) csc += n;
    }
    float ss = s;
    #pragma unroll
    for (int o = 16; o > 0; o >>= 1) ss += __shfl_xor_sync(0xffffffffu, ss, o);

    __shared__ int   wtot[8];
    __shared__ float wsum[8];
    __shared__ int   wbase[9];
    __shared__ float s_rs;
    if (lane == 31) wtot[w] = csc;
    if (lane == 0)  wsum[w] = ss;
    __syncthreads();
    if (t == 0) {
        int acc = 0; float rs = 0.f;
        #pragma unroll
        for (int k = 0; k < 8; k++) { wbase[k] = acc; acc += wtot[k]; rs += wsum[k]; }
        wbase[8] = acc; s_rs = rs;
    }
    __syncthreads();

    int pos = wbase[w] + csc - c;
    size_t ob = (size_t)row * NNZCAP;
    int basecol = t * 8;
    #pragma unroll
    for (int i = 0; i < 8; i++) {
        if ((em >> i) & 1u) {
            if (pos < NNZCAP) { g_col[ob + pos] = basecol + i; g_val[ob + pos] = v[i]; }
            pos++;
        }
    }
    if (t == 0) {
        int total = wbase[8];
        float rs = s_rs;
        g_cnt[row]  = (total < NNZCAP) ? total : NNZCAP;
        g_dg[row]   = 1.f / sqrtf(rs + 1.f);
        g_mask[row] = (rs > 0.f) ? 1.f : 0.f;
        g_need[row] = 0;
    }
}

// L2: alpha[n] = sigmoid( (dg_n*(sum_nbr val*dg*y + dg_n*y_n) + b)^2 )
__global__ void k_alpha(const float* __restrict__ bptr) {
    int row  = blockIdx.x * 8 + (threadIdx.x >> 5);
    int lane = threadIdx.x & 31;
    int nb   = (row >> 11) << 11;
    int cnt  = g_cnt[row];
    size_t base = (size_t)row * NNZCAP;
    float z = 0.f;
    for (int e = lane; e < cnt; e += 32) {
        int nc = nb + g_col[base + e];
        z += g_val[base + e] * g_dg[nc] * g_y[nc];
    }
    #pragma unroll
    for (int o = 16; o > 0; o >>= 1) z += __shfl_down_sync(0xffffffffu, z, o);
    if (lane == 0) {
        float dgn = g_dg[row];
        float ap  = dgn * (z + dgn * g_y[row]) + bptr[0];
        float tt  = ap * ap;
        g_alpha[row] = 1.f / (1.f + expf(-tt));
    }
}

// block-wide inclusive scan, 1024 threads (32 warps). wsum: shared int[32].
__device__ __forceinline__ int bscan1024(int v, int lane, int w, int* wsum) {
    __syncthreads();
    int x = v;
    #pragma unroll
    for (int o = 1; o < 32; o <<= 1) {
        int n = __shfl_up_sync(0xffffffffu, x, o);
        if (lane >= o) x += n;
    }
    if (lane == 31) wsum[w] = x;
    __syncthreads();
    if (w == 0) {
        int s = wsum[lane];
        #pragma unroll
        for (int o = 1; o < 32; o <<= 1) {
            int n = __shfl_up_sync(0xffffffffu, s, o);
            if (lane >= o) s += n;
        }
        wsum[lane] = s;
    }
    __syncthreads();
    if (w > 0) x += wsum[w - 1];
    return x;
}

// L3: histogram radix-select + 512 bitonic (exact lax.top_k order),
// cut, topi, cut_alpha, active list/colmap, mark rows needed by T.
__global__ void k_topk(float* __restrict__ out, long long out_size) {
    int b = blockIdx.x;
    int t = threadIdx.x;  // 1024
    int lane = t & 31, w = t >> 5;
    int nb = b << 11;
    __shared__ int hist[1024];
    __shared__ int wsum[32];
    __shared__ unsigned long long cand[512];
    __shared__ int s_T, s_C, s_acnt;
    __shared__ float s_cut;

    hist[t] = 0;
    if (t == 0) s_C = 0;
    __syncthreads();

    unsigned b0 = __float_as_uint(g_alpha[nb + 2*t]);
    unsigned b1 = __float_as_uint(g_alpha[nb + 2*t + 1]);
    int bin0 = (int)(b0 >> 13) - 0x1F800; bin0 = bin0 < 0 ? 0 : (bin0 > 1023 ? 1023 : bin0);
    int bin1 = (int)(b1 >> 13) - 0x1F800; bin1 = bin1 < 0 ? 0 : (bin1 > 1023 ? 1023 : bin1);
    atomicAdd(&hist[bin0], 1);
    atomicAdd(&hist[bin1], 1);
    __syncthreads();

    int r = 1023 - t;
    int hv = hist[r];
    int sufi = bscan1024(hv, lane, w, wsum);
    int sufn = sufi - hv;
    if (sufi >= KK && sufn < KK) s_T = r;
    __syncthreads();
    int T = s_T;

    if (bin0 >= T) {
        int p = atomicAdd(&s_C, 1);
        if (p < 512) cand[p] = ((unsigned long long)(0xFFFFFFFFu - b0) << 32) | (unsigned)(2*t);
    }
    if (bin1 >= T) {
        int p = atomicAdd(&s_C, 1);
        if (p < 512) cand[p] = ((unsigned long long)(0xFFFFFFFFu - b1) << 32) | (unsigned)(2*t + 1);
    }
    __syncthreads();
    int C = s_C < 512 ? s_C : 512;
    if (t >= C && t < 512) cand[t] = 0xFFFFFFFFFFFFFFFFULL;
    __syncthreads();

    for (int sz = 2; sz <= 512; sz <<= 1) {
        for (int st = sz >> 1; st > 0; st >>= 1) {
            if (t < 512) {
                int p = t ^ st;
                if (p > t) {
                    bool up = ((t & sz) == 0);
                    unsigned long long a = cand[t], c2 = cand[p];
                    if ((a > c2) == up) { cand[t] = c2; cand[p] = a; }
                }
            }
            __syncthreads();
        }
    }

    if (t == 0) {
        unsigned vb = 0xFFFFFFFFu - (unsigned)(cand[KK - 1] >> 32);
        s_cut = __uint_as_float(vb);
    }
    if (t < KK) {
        int idx = (int)(cand[t] & 0xFFFFFFFFULL);
        long long o = (long long)OFF_TI + (long long)b * KK + t;
        if (o < out_size) out[o] = (float)idx;
    }
    __syncthreads();
    float cut = s_cut;

    int j0 = 2*t, j1 = 2*t + 1;
    float ca0 = fmaxf((__uint_as_float(b0) + 1e-7f) - cut, 0.f);
    float ca1 = fmaxf((__uint_as_float(b1) + 1e-7f) - cut, 0.f);
    g_ca[nb + j0] = ca0;
    g_ca[nb + j1] = ca1;
    int p0 = ca0 > 0.f ? 1 : 0, p1 = ca1 > 0.f ? 1 : 0;
    int incl = bscan1024(p0 + p1, lane, w, wsum);
    int excl = incl - (p0 + p1);
    if (p0) { int pos = excl;      if (pos < ACAP) { g_cmap[nb+j0] = pos; g_aidx[b*ACAP+pos] = j0; } else g_cmap[nb+j0] = -1; }
    else g_cmap[nb + j0] = -1;
    if (p1) { int pos = excl + p0; if (pos < ACAP) { g_cmap[nb+j1] = pos; g_aidx[b*ACAP+pos] = j1; } else g_cmap[nb+j1] = -1; }
    else g_cmap[nb + j1] = -1;
    if (t == 1023) s_acnt = (incl < ACAP) ? incl : ACAP;
    __syncthreads();
    int AC = s_acnt;
    if (t == 1023) g_acnt[b] = AC;

    for (int p = t; p < AC; p += 1024) {
        int j = g_aidx[b * ACAP + p];
        int rowj = nb + j;
        g_need[rowj] = 1;
        int c = g_cnt[rowj];
        size_t ba = (size_t)rowj * NNZCAP;
        for (int e = 0; e < c; e++) g_need[nb + g_col[ba + e]] = 1;
    }
}

// L4: WARP per row. Two passes over the row's CSR edges; all reductions via
// shfl/ballot, no block barriers. Produces compact Sc (vals + j + count +
// packed mask/base). 2048 blocks x 256 threads (8 warps).
__global__ void k_Sc() {
    __shared__ int   sh_a[8][SCCAP];
    __shared__ int   sh_j[8][SCCAP];
    __shared__ float sh_v[8][SCCAP];

    int t = threadIdx.x, lane = t & 31, wp = t >> 5;
    int row = blockIdx.x * 8 + wp;
    int b = row >> 11, i = row & 2047, nb = b << 11;
    int cnt = g_cnt[row];
    size_t base = (size_t)row * NNZCAP;

    int   selfA   = g_cmap[row];
    float dgi     = g_dg[row];
    float selfVal = dgi * g_ca[row];
    unsigned full = 0xffffffffu;
    unsigned ltm = (1u << lane) - 1u;

    // ---- pass 1: rowsum, cntLess, diag detection ----
    float rowsum = 0.f; int cntLess = 0; bool diagL = false;
    for (int e = lane; e < cnt; e += 32) {
        int j = g_col[base + e];
        int nc = nb + j;
        int a = g_cmap[nc];
        if (a >= 0) {
            float sv = g_val[base + e] * g_dg[nc] * g_ca[nc];
            if (j == i) { sv += selfVal; diagL = true; }
            rowsum += sv;
            if (j < i) cntLess++;
        }
    }
    #pragma unroll
    for (int o = 16; o > 0; o >>= 1) {
        rowsum  += __shfl_xor_sync(full, rowsum, o);
        cntLess += __shfl_xor_sync(full, cntLess, o);
    }
    bool diag = __any_sync(full, diagL);
    bool selfIns = (selfA >= 0) && !diag;
    if (selfIns) rowsum += selfVal;

    // ---- pass 2: ordered placement into per-warp smem ----
    int nsBase = 0;
    for (int e0 = 0; e0 < cnt; e0 += 32) {
        int e = e0 + lane;
        bool act = false; int j = 0, a = -1; float sv = 0.f;
        if (e < cnt) {
            j = g_col[base + e];
            int nc = nb + j;
            a = g_cmap[nc];
            if (a >= 0) {
                act = true;
                sv = g_val[base + e] * g_dg[nc] * g_ca[nc];
                if (j == i) sv += selfVal;
            }
        }
        unsigned m = __ballot_sync(full, act);
        if (act) {
            int pos = nsBase + __popc(m & ltm) + ((selfIns && j > i) ? 1 : 0);
            if (pos < SCCAP) { sh_a[wp][pos] = a; sh_j[wp][pos] = j; sh_v[wp][pos] = sv; }
        }
        nsBase += __popc(m);
    }
    if (selfIns && lane == 0 && cntLess < SCCAP) {
        sh_a[wp][cntLess] = selfA; sh_j[wp][cntLess] = i; sh_v[wp][cntLess] = selfVal;
    }
    int ns = nsBase + (selfIns ? 1 : 0);
    if (ns > SCCAP) ns = SCCAP;
    __syncwarp(full);

    float factor = g_mask[row] * dgi;
    float denom  = fmaxf(factor * rowsum, 1e-12f);
    float scale  = factor / denom;

    // masks + popc bases: lanes 0..NWORD-1
    unsigned mw = 0;
    if (lane < NWORD) {
        for (int q = 0; q < ns; q++)
            if ((sh_a[wp][q] >> 5) == lane) mw |= 1u << (sh_a[wp][q] & 31);
    }
    int pc = __popc(mw);
    int px = pc;
    #pragma unroll
    for (int o = 1; o < 16; o <<= 1) {
        int n = __shfl_up_sync(full, px, o);
        if (lane >= o) px += n;
    }
    if (lane < NWORD) g_scmb[row * NWORD + lane] = make_uint2(mw, (unsigned)(px - pc));

    for (int q = lane; q < ns; q += 32) {
        g_scvals[(size_t)row * SCCAP + q] = sh_v[wp][q] * scale;
        g_scj  [(size_t)row * SCCAP + q] = sh_j[wp][q];
    }
    if (lane == 0) g_scn[row] = ns;
}

// L5 (320 thr), fused segments:
//  A [0, 2560):            x_c active rows (compute).
//  B [2560, 18944):        Tt for needed rows (latency-bound).
//  C [18944, 35328):       dense S row write (zero + patches) + inactive-x_c zeros.
//  D [35328, 51712):       inactive coarse rows: pure zero-fill.
__global__ void k_Txc(const float* __restrict__ x, float* __restrict__ out) {
    int t = threadIdx.x;   // 320
    unsigned bid = blockIdx.x;
    float4 z = make_float4(0.f, 0.f, 0.f, 0.f);

    if (bid < BB * ACAP) {
        int b = bid / ACAP, a = bid % ACAP;
        int AC = g_acnt[b];
        if (a >= AC) return;
        int nb = b << 11;
        int m = g_aidx[b * ACAP + a];
        int row = nb + m;
        int cnt = g_cnt[row];
        size_t base = (size_t)row * NNZCAP;

        __shared__ float s_w[NNZCAP];
        __shared__ int   s_nr[NNZCAP];
        __shared__ int   s_diag;
        if (t == 0) s_diag = 0;
        __syncthreads();
        for (int e = t; e < cnt; e += 320) {
            int jj = g_col[base + e];
            int nr = nb + jj;
            s_nr[e] = nr;
            s_w[e] = sc_lookup(nr, a);
            if (jj == m) s_diag = 1;
        }
        __syncthreads();
        if (t < FD) {
            float acc = 0.f;
            for (int e = 0; e < cnt; e++) acc += s_w[e] * x[(size_t)s_nr[e] * FD + t];
            if (!s_diag) acc += sc_lookup(row, a) * x[(size_t)row * FD + t];
            out[OFF_XC + (size_t)row * FD + t] = acc;
        }
    } else if (bid < BB * ACAP + BB * NN) {
        int row = bid - BB * ACAP;
        if (!g_need[row]) return;
        int b = row >> 11, nb = b << 11;
        int AC = g_acnt[b];
        int cnt = g_cnt[row];
        size_t base = (size_t)row * NNZCAP;
        int widx = t >> 5, lane = t & 31;
        unsigned ltm = (1u << lane) - 1u;

        __shared__ float s_v[32];
        __shared__ int   s_rn[32];
        __shared__ uint2 s_mb[32 * NWORD];

        float acc = 0.f;
        for (int c0 = 0; c0 < cnt; c0 += 32) {
            int nch = cnt - c0; if (nch > 32) nch = 32;
            __syncthreads();
            if (t < nch) {
                s_rn[t] = nb + g_col[base + c0 + t];
                s_v[t]  = g_val[base + c0 + t];
            }
            __syncthreads();
            {
                int e = t & 31, w2 = t >> 5;   // 320 = 32 x 10 exactly
                if (e < nch) s_mb[e * NWORD + w2] = g_scmb[s_rn[e] * NWORD + w2];
            }
            __syncthreads();
            for (int e = 0; e < nch; e++) {
                uint2 mb = s_mb[e * NWORD + widx];
                if ((mb.x >> lane) & 1u) {
                    int pos = (int)mb.y + __popc(mb.x & ltm);
                    acc += s_v[e] * g_scvals[(size_t)s_rn[e] * SCCAP + pos];
                }
            }
        }
        if (t < AC) g_Tt[(size_t)row * ACAP + t] = acc;
    } else if (bid < BB * ACAP + 2u * BB * NN) {
        // ---- seg C: S dense row + inactive x_c zeros ----
        int row = bid - (BB * ACAP + BB * NN);
        float4* op = (float4*)(out + OFF_S + (size_t)row * NN);
        #pragma unroll 2
        for (int i = t; i < NN / 4; i += 320) __stcs(op + i, z);
        if (g_cmap[row] < 0 && t < FD / 4)
            __stcs((float4*)(out + OFF_XC + (size_t)row * FD) + t, z);
        __syncthreads();
        int ns = g_scn[row];
        if (t < ns)
            out[OFF_S + (size_t)row * NN + g_scj[(size_t)row * SCCAP + t]] =
                g_scvals[(size_t)row * SCCAP + t];
    } else {
        // ---- seg D: inactive coarse rows: pure zero-fill ----
        int row = bid - (BB * ACAP + 2u * BB * NN);
        if (g_cmap[row] >= 0) return;   // active rows written in k_tail
        float4* co = (float4*)(out + OFF_CO + (size_t)row * NN);
        #pragma unroll 2
        for (int i = t; i < NN / 4; i += 320) __stcs(co + i, z);
    }
}

// L6: coarse core: g_cact[a][c] = sum_{k in nbr(j_c) U {j_c}} Sc[k,c]*Tt[k,a]
__global__ void k_cact() {
    int b = blockIdx.x / ACAP, c = blockIdx.x % ACAP;
    int AC = g_acnt[b];
    if (c >= AC) return;
    int nb = b << 11;
    int j = g_aidx[b * ACAP + c];
    int rowj = nb + j;
    int cnt = g_cnt[rowj];
    size_t base = (size_t)rowj * NNZCAP;
    int t = threadIdx.x;  // 320

    __shared__ float s_w[NNZCAP];
    __shared__ int   s_kr[NNZCAP];
    __shared__ int   s_diag;
    if (t == 0) s_diag = 0;
    __syncthreads();
    for (int e = t; e < cnt; e += 320) {
        int k = g_col[base + e];
        int kr = nb + k;
        s_kr[e] = kr;
        s_w[e] = sc_lookup(kr, c);
        if (k == j) s_diag = 1;
    }
    __syncthreads();

    if (t < AC) {
        float acc = 0.f;
        for (int e = 0; e < cnt; e++) {
            float ww = s_w[e];
            if (ww != 0.f) acc += ww * g_Tt[(size_t)s_kr[e] * ACAP + t];
        }
        if (!s_diag) {
            float ww = sc_lookup(rowj, c);
            if (ww != 0.f) acc += ww * g_Tt[(size_t)rowj * ACAP + t];
        }
        g_cact[(size_t)b * ACAP * ACAP + (size_t)t * ACAP + c] = acc;
    }
}

// L7: active coarse rows only: zero-fill + quantized patches (~13MB).
__global__ void k_tail(float* __restrict__ out) {
    int b = blockIdx.x / ACAP, a = blockIdx.x % ACAP;
    int AC = g_acnt[b];
    if (a >= AC) return;
    int t = threadIdx.x;   // 256
    int nb = b << 11;
    int row = nb + g_aidx[b * ACAP + a];
    float4 z = make_float4(0.f, 0.f, 0.f, 0.f);
    float4* co = (float4*)(out + OFF_CO + (size_t)row * NN);
    #pragma unroll 2
    for (int i = t; i < NN / 4; i += 256) __stcs(co + i, z);
    __syncthreads();
    const float* crow = g_cact + (size_t)b * ACAP * ACAP + (size_t)a * ACAP;
    const int* ai = g_aidx + b * ACAP;
    for (int c = t; c < AC; c += 256) {
        float q = floorf(crow[c] * 10000.0f) / 10000.0f;
        out[OFF_CO + (size_t)row * NN + ai[c]] = q;
    }
}

extern "C" void kernel_launch(void* const* d_in, const int* in_sizes, int n_in,
                              void* d_out, int out_size) {
    const float* x    = (const float*)d_in[0];
    const float* adj  = (const float*)d_in[1];
    const float* W    = (const float*)d_in[2];
    const float* bptr = (const float*)d_in[3];
    float* out = (float*)d_out;

    k_head  <<<BB * NN + BB * NN / 8, 256>>>(adj, x, W);        // 1
    k_alpha <<<BB * NN / 8, 256>>>(bptr);                       // 2
    k_topk  <<<BB, 1024>>>(out, (long long)out_size);           // 3
    k_Sc    <<<BB * NN / 8, 256>>>();                           // 4 (ncu slot)
    k_Txc   <<<BB * ACAP + 3 * BB * NN, 320>>>(x, out);         // 5
    k_cact  <<<BB * ACAP, 320>>>();                             // 6
    k_tail  <<<BB * ACAP, 256>>>(out);                          // 7
}

// round 17
// speedup vs baseline: 1.3333x; 1.1659x over previous
#include <cuda_runtime.h>
#include <math.h>

#define BB 8
#define NN 2048
#define FD 256
#define KK 205          // int(2048*0.1)+1
#define ACAP 320        // active-column capacity (expected ~205)
#define NNZCAP 256      // nnz-per-row capacity (expected ~41)
#define SCCAP 48        // active entries per Sc row (expected ~4)

// ---- output layout (concatenated f32): x_c | coarse | S | topi ----
#define OFF_XC 0ULL
#define OFF_CO 4194304ULL                 // 8*2048*256
#define OFF_S  37748736ULL                // + 8*2048*2048
#define OFF_TI 71303168ULL                // + 8*2048*2048

// ---- device scratch ----
__device__ float    g_dg   [BB*NN];
__device__ float    g_mask [BB*NN];
__device__ float    g_y    [BB*NN];
__device__ float    g_alpha[BB*NN];
__device__ float    g_ca   [BB*NN];
__device__ int      g_cnt  [BB*NN];
__device__ int      g_need [BB*NN];
__device__ int      g_col  [(size_t)BB*NN*NNZCAP];
__device__ float    g_val  [(size_t)BB*NN*NNZCAP];
__device__ int      g_aidx [BB*ACAP];
__device__ int      g_acnt [BB];
__device__ int      g_cmap [BB*NN];
__device__ float    g_scvals[(size_t)BB*NN*SCCAP];   // compact Sc values (a-ascending)
__device__ int      g_scj  [(size_t)BB*NN*SCCAP];    // column index j per compact entry
__device__ int      g_scn  [BB*NN];                  // compact count per row
__device__ float    g_ScD  [(size_t)BB*NN*ACAP];     // DENSE Sc row [row][a] (21MB, L2-resident)
__device__ float    g_Tt   [(size_t)BB*NN*ACAP];
__device__ float    g_cact [(size_t)BB*ACAP*ACAP];   // coarse active core [a][c]

// ---------------------------------------------------------------
// L1: fused head. blocks [0,16384): rowstats. blocks [16384,18432): raw y.
// ---------------------------------------------------------------
__global__ void k_head(const float* __restrict__ adj,
                       const float* __restrict__ x,
                       const float* __restrict__ W) {
    int t = threadIdx.x;               // 256
    int lane = t & 31, w = t >> 5;

    if (blockIdx.x >= BB * NN) {
        int row = (blockIdx.x - BB * NN) * 8 + w;
        const float* xr = x + (size_t)row * FD;
        float s = 0.f;
        #pragma unroll
        for (int f = lane; f < FD; f += 32) s += xr[f] * W[f];
        #pragma unroll
        for (int o = 16; o > 0; o >>= 1) s += __shfl_down_sync(0xffffffffu, s, o);
        if (lane == 0) g_y[row] = s;
        return;
    }

    int row = blockIdx.x;
    const float* ar = adj + (size_t)row * NN;

    float v[8];
    float4 u0 = __ldcs(((const float4*)ar) + t * 2);
    float4 u1 = __ldcs(((const float4*)ar) + t * 2 + 1);
    v[0]=u0.x; v[1]=u0.y; v[2]=u0.z; v[3]=u0.w;
    v[4]=u1.x; v[5]=u1.y; v[6]=u1.z; v[7]=u1.w;

    float s = 0.f; int c = 0; unsigned em = 0;
    #pragma unroll
    for (int i = 0; i < 8; i++) { s += v[i]; if (v[i] != 0.f) { c++; em |= 1u << i; } }

    int csc = c;
    #pragma unroll
    for (int o = 1; o < 32; o <<= 1) {
        int n = __shfl_up_sync(0xffffffffu, csc, o);
        if (lane >= o) csc += n;
    }
    float ss = s;
    #pragma unroll
    for (int o = 16; o > 0; o >>= 1) ss += __shfl_xor_sync(0xffffffffu, ss, o);

    __shared__ int   wtot[8];
    __shared__ float wsum[8];
    __shared__ int   wbase[9];
    __shared__ float s_rs;
    if (lane == 31) wtot[w] = csc;
    if (lane == 0)  wsum[w] = ss;
    __syncthreads();
    if (t == 0) {
        int acc = 0; float rs = 0.f;
        #pragma unroll
        for (int k = 0; k < 8; k++) { wbase[k] = acc; acc += wtot[k]; rs += wsum[k]; }
        wbase[8] = acc; s_rs = rs;
    }
    __syncthreads();

    int pos = wbase[w] + csc - c;
    size_t ob = (size_t)row * NNZCAP;
    int basecol = t * 8;
    #pragma unroll
    for (int i = 0; i < 8; i++) {
        if ((em >> i) & 1u) {
            if (pos < NNZCAP) { g_col[ob + pos] = basecol + i; g_val[ob + pos] = v[i]; }
            pos++;
        }
    }
    if (t == 0) {
        int total = wbase[8];
        float rs = s_rs;
        g_cnt[row]  = (total < NNZCAP) ? total : NNZCAP;
        g_dg[row]   = 1.f / sqrtf(rs + 1.f);
        g_mask[row] = (rs > 0.f) ? 1.f : 0.f;
        g_need[row] = 0;
    }
}

// L2: alpha[n] = sigmoid( (dg_n*(sum_nbr val*dg*y + dg_n*y_n) + b)^2 )
__global__ void k_alpha(const float* __restrict__ bptr) {
    int row  = blockIdx.x * 8 + (threadIdx.x >> 5);
    int lane = threadIdx.x & 31;
    int nb   = (row >> 11) << 11;
    int cnt  = g_cnt[row];
    size_t base = (size_t)row * NNZCAP;
    float z = 0.f;
    for (int e = lane; e < cnt; e += 32) {
        int nc = nb + g_col[base + e];
        z += g_val[base + e] * g_dg[nc] * g_y[nc];
    }
    #pragma unroll
    for (int o = 16; o > 0; o >>= 1) z += __shfl_down_sync(0xffffffffu, z, o);
    if (lane == 0) {
        float dgn = g_dg[row];
        float ap  = dgn * (z + dgn * g_y[row]) + bptr[0];
        float tt  = ap * ap;
        g_alpha[row] = 1.f / (1.f + expf(-tt));
    }
}

// block-wide inclusive scan, 1024 threads (32 warps). wsum: shared int[32].
__device__ __forceinline__ int bscan1024(int v, int lane, int w, int* wsum) {
    __syncthreads();
    int x = v;
    #pragma unroll
    for (int o = 1; o < 32; o <<= 1) {
        int n = __shfl_up_sync(0xffffffffu, x, o);
        if (lane >= o) x += n;
    }
    if (lane == 31) wsum[w] = x;
    __syncthreads();
    if (w == 0) {
        int s = wsum[lane];
        #pragma unroll
        for (int o = 1; o < 32; o <<= 1) {
            int n = __shfl_up_sync(0xffffffffu, s, o);
            if (lane >= o) s += n;
        }
        wsum[lane] = s;
    }
    __syncthreads();
    if (w > 0) x += wsum[w - 1];
    return x;
}

// L3: histogram radix-select + 512 bitonic (exact lax.top_k order),
// cut, topi, cut_alpha, active list/colmap, mark rows needed by T.
__global__ void k_topk(float* __restrict__ out, long long out_size) {
    int b = blockIdx.x;
    int t = threadIdx.x;  // 1024
    int lane = t & 31, w = t >> 5;
    int nb = b << 11;
    __shared__ int hist[1024];
    __shared__ int wsum[32];
    __shared__ unsigned long long cand[512];
    __shared__ int s_T, s_C, s_acnt;
    __shared__ float s_cut;

    hist[t] = 0;
    if (t == 0) s_C = 0;
    __syncthreads();

    unsigned b0 = __float_as_uint(g_alpha[nb + 2*t]);
    unsigned b1 = __float_as_uint(g_alpha[nb + 2*t + 1]);
    int bin0 = (int)(b0 >> 13) - 0x1F800; bin0 = bin0 < 0 ? 0 : (bin0 > 1023 ? 1023 : bin0);
    int bin1 = (int)(b1 >> 13) - 0x1F800; bin1 = bin1 < 0 ? 0 : (bin1 > 1023 ? 1023 : bin1);
    atomicAdd(&hist[bin0], 1);
    atomicAdd(&hist[bin1], 1);
    __syncthreads();

    int r = 1023 - t;
    int hv = hist[r];
    int sufi = bscan1024(hv, lane, w, wsum);
    int sufn = sufi - hv;
    if (sufi >= KK && sufn < KK) s_T = r;
    __syncthreads();
    int T = s_T;

    if (bin0 >= T) {
        int p = atomicAdd(&s_C, 1);
        if (p < 512) cand[p] = ((unsigned long long)(0xFFFFFFFFu - b0) << 32) | (unsigned)(2*t);
    }
    if (bin1 >= T) {
        int p = atomicAdd(&s_C, 1);
        if (p < 512) cand[p] = ((unsigned long long)(0xFFFFFFFFu - b1) << 32) | (unsigned)(2*t + 1);
    }
    __syncthreads();
    int C = s_C < 512 ? s_C : 512;
    if (t >= C && t < 512) cand[t] = 0xFFFFFFFFFFFFFFFFULL;
    __syncthreads();

    for (int sz = 2; sz <= 512; sz <<= 1) {
        for (int st = sz >> 1; st > 0; st >>= 1) {
            if (t < 512) {
                int p = t ^ st;
                if (p > t) {
                    bool up = ((t & sz) == 0);
                    unsigned long long a = cand[t], c2 = cand[p];
                    if ((a > c2) == up) { cand[t] = c2; cand[p] = a; }
                }
            }
            __syncthreads();
        }
    }

    if (t == 0) {
        unsigned vb = 0xFFFFFFFFu - (unsigned)(cand[KK - 1] >> 32);
        s_cut = __uint_as_float(vb);
    }
    if (t < KK) {
        int idx = (int)(cand[t] & 0xFFFFFFFFULL);
        long long o = (long long)OFF_TI + (long long)b * KK + t;
        if (o < out_size) out[o] = (float)idx;
    }
    __syncthreads();
    float cut = s_cut;

    int j0 = 2*t, j1 = 2*t + 1;
    float ca0 = fmaxf((__uint_as_float(b0) + 1e-7f) - cut, 0.f);
    float ca1 = fmaxf((__uint_as_float(b1) + 1e-7f) - cut, 0.f);
    g_ca[nb + j0] = ca0;
    g_ca[nb + j1] = ca1;
    int p0 = ca0 > 0.f ? 1 : 0, p1 = ca1 > 0.f ? 1 : 0;
    int incl = bscan1024(p0 + p1, lane, w, wsum);
    int excl = incl - (p0 + p1);
    if (p0) { int pos = excl;      if (pos < ACAP) { g_cmap[nb+j0] = pos; g_aidx[b*ACAP+pos] = j0; } else g_cmap[nb+j0] = -1; }
    else g_cmap[nb + j0] = -1;
    if (p1) { int pos = excl + p0; if (pos < ACAP) { g_cmap[nb+j1] = pos; g_aidx[b*ACAP+pos] = j1; } else g_cmap[nb+j1] = -1; }
    else g_cmap[nb + j1] = -1;
    if (t == 1023) s_acnt = (incl < ACAP) ? incl : ACAP;
    __syncthreads();
    int AC = s_acnt;
    if (t == 1023) g_acnt[b] = AC;

    for (int p = t; p < AC; p += 1024) {
        int j = g_aidx[b * ACAP + p];
        int rowj = nb + j;
        g_need[rowj] = 1;
        int c = g_cnt[rowj];
        size_t ba = (size_t)rowj * NNZCAP;
        for (int e = 0; e < c; e++) g_need[nb + g_col[ba + e]] = 1;
    }
}

// L4: WARP per row. Two passes over the row's CSR edges, all shfl/ballot.
// Produces compact (vals, j, count) for the S patch AND the dense ScD row.
__global__ void k_Sc() {
    __shared__ int   sh_a[8][SCCAP];
    __shared__ int   sh_j[8][SCCAP];
    __shared__ float sh_v[8][SCCAP];

    int t = threadIdx.x, lane = t & 31, wp = t >> 5;
    int row = blockIdx.x * 8 + wp;
    int b = row >> 11, i = row & 2047, nb = b << 11;
    int cnt = g_cnt[row];
    size_t base = (size_t)row * NNZCAP;

    int   selfA   = g_cmap[row];
    float dgi     = g_dg[row];
    float selfVal = dgi * g_ca[row];
    unsigned full = 0xffffffffu;
    unsigned ltm = (1u << lane) - 1u;

    // ---- pass 1: rowsum, cntLess, diag detection ----
    float rowsum = 0.f; int cntLess = 0; bool diagL = false;
    for (int e = lane; e < cnt; e += 32) {
        int j = g_col[base + e];
        int nc = nb + j;
        int a = g_cmap[nc];
        if (a >= 0) {
            float sv = g_val[base + e] * g_dg[nc] * g_ca[nc];
            if (j == i) { sv += selfVal; diagL = true; }
            rowsum += sv;
            if (j < i) cntLess++;
        }
    }
    #pragma unroll
    for (int o = 16; o > 0; o >>= 1) {
        rowsum  += __shfl_xor_sync(full, rowsum, o);
        cntLess += __shfl_xor_sync(full, cntLess, o);
    }
    bool diag = __any_sync(full, diagL);
    bool selfIns = (selfA >= 0) && !diag;
    if (selfIns) rowsum += selfVal;

    // ---- pass 2: ordered placement into per-warp smem ----
    int nsBase = 0;
    for (int e0 = 0; e0 < cnt; e0 += 32) {
        int e = e0 + lane;
        bool act = false; int j = 0, a = -1; float sv = 0.f;
        if (e < cnt) {
            j = g_col[base + e];
            int nc = nb + j;
            a = g_cmap[nc];
            if (a >= 0) {
                act = true;
                sv = g_val[base + e] * g_dg[nc] * g_ca[nc];
                if (j == i) sv += selfVal;
            }
        }
        unsigned m = __ballot_sync(full, act);
        if (act) {
            int pos = nsBase + __popc(m & ltm) + ((selfIns && j > i) ? 1 : 0);
            if (pos < SCCAP) { sh_a[wp][pos] = a; sh_j[wp][pos] = j; sh_v[wp][pos] = sv; }
        }
        nsBase += __popc(m);
    }
    if (selfIns && lane == 0 && cntLess < SCCAP) {
        sh_a[wp][cntLess] = selfA; sh_j[wp][cntLess] = i; sh_v[wp][cntLess] = selfVal;
    }
    int ns = nsBase + (selfIns ? 1 : 0);
    if (ns > SCCAP) ns = SCCAP;
    __syncwarp(full);

    float factor = g_mask[row] * dgi;
    float denom  = fmaxf(factor * rowsum, 1e-12f);
    float scale  = factor / denom;

    // dense ScD row: zero then patch
    size_t sb = (size_t)row * ACAP;
    float4* dp = (float4*)(g_ScD + sb);
    float4 z4 = make_float4(0.f, 0.f, 0.f, 0.f);
    #pragma unroll
    for (int q = lane; q < ACAP / 4; q += 32) dp[q] = z4;
    __syncwarp(full);
    for (int q = lane; q < ns; q += 32) {
        float sv = sh_v[wp][q] * scale;
        g_ScD[sb + sh_a[wp][q]] = sv;
        g_scvals[(size_t)row * SCCAP + q] = sv;
        g_scj  [(size_t)row * SCCAP + q] = sh_j[wp][q];
    }
    if (lane == 0) g_scn[row] = ns;
}

// L5 (320 thr), fused segments:
//  A [0, 2560):       x_c active rows (compute).
//  B [2560, 18944):   Tt for needed rows — barrier-free coalesced L2 loop.
//  C [18944, 35328):  dense S row write (zero + patches) + inactive-x_c zeros.
//  D [35328, 51712):  inactive coarse rows: pure zero-fill.
__global__ void k_Txc(const float* __restrict__ x, float* __restrict__ out) {
    int t = threadIdx.x;   // 320
    unsigned bid = blockIdx.x;
    float4 z = make_float4(0.f, 0.f, 0.f, 0.f);

    if (bid < BB * ACAP) {
        int b = bid / ACAP, a = bid % ACAP;
        int AC = g_acnt[b];
        if (a >= AC) return;
        int nb = b << 11;
        int m = g_aidx[b * ACAP + a];
        int row = nb + m;
        int cnt = g_cnt[row];
        size_t base = (size_t)row * NNZCAP;

        __shared__ float s_w[NNZCAP];
        __shared__ int   s_nr[NNZCAP];
        __shared__ int   s_diag;
        if (t == 0) s_diag = 0;
        __syncthreads();
        for (int e = t; e < cnt; e += 320) {
            int jj = g_col[base + e];
            int nr = nb + jj;
            s_nr[e] = nr;
            s_w[e] = g_ScD[(size_t)nr * ACAP + a];
            if (jj == m) s_diag = 1;
        }
        __syncthreads();
        if (t < FD) {
            float acc = 0.f;
            for (int e = 0; e < cnt; e++) acc += s_w[e] * x[(size_t)s_nr[e] * FD + t];
            if (!s_diag) acc += g_ScD[(size_t)row * ACAP + a] * x[(size_t)row * FD + t];
            out[OFF_XC + (size_t)row * FD + t] = acc;
        }
    } else if (bid < BB * ACAP + BB * NN) {
        // ---- seg B: Tt[k,t] = sum_e val[e] * ScD[rn[e], t] ----
        int row = bid - BB * ACAP;
        if (!g_need[row]) return;
        int b = row >> 11, nb = b << 11;
        int AC = g_acnt[b];
        int cnt = g_cnt[row];
        size_t base = (size_t)row * NNZCAP;

        __shared__ float s_v[NNZCAP];
        __shared__ int   s_rn[NNZCAP];
        for (int e = t; e < cnt; e += 320) {
            s_rn[e] = nb + g_col[base + e];
            s_v[e]  = g_val[base + e];
        }
        __syncthreads();
        float acc = 0.f;
        int e = 0;
        #pragma unroll 1
        for (; e + 4 <= cnt; e += 4) {
            float a0 = g_ScD[(size_t)s_rn[e]     * ACAP + t];
            float a1 = g_ScD[(size_t)s_rn[e + 1] * ACAP + t];
            float a2 = g_ScD[(size_t)s_rn[e + 2] * ACAP + t];
            float a3 = g_ScD[(size_t)s_rn[e + 3] * ACAP + t];
            acc += s_v[e] * a0;
            acc += s_v[e + 1] * a1;
            acc += s_v[e + 2] * a2;
            acc += s_v[e + 3] * a3;
        }
        for (; e < cnt; e++) acc += s_v[e] * g_ScD[(size_t)s_rn[e] * ACAP + t];
        if (t < AC) g_Tt[(size_t)row * ACAP + t] = acc;
    } else if (bid < BB * ACAP + 2u * BB * NN) {
        // ---- seg C: S dense row + inactive x_c zeros ----
        int row = bid - (BB * ACAP + BB * NN);
        float4* op = (float4*)(out + OFF_S + (size_t)row * NN);
        #pragma unroll 2
        for (int i = t; i < NN / 4; i += 320) __stcs(op + i, z);
        if (g_cmap[row] < 0 && t < FD / 4)
            __stcs((float4*)(out + OFF_XC + (size_t)row * FD) + t, z);
        __syncthreads();
        int ns = g_scn[row];
        if (t < ns)
            out[OFF_S + (size_t)row * NN + g_scj[(size_t)row * SCCAP + t]] =
                g_scvals[(size_t)row * SCCAP + t];
    } else {
        // ---- seg D: inactive coarse rows: pure zero-fill ----
        int row = bid - (BB * ACAP + 2u * BB * NN);
        if (g_cmap[row] >= 0) return;   // active rows written in k_tail
        float4* co = (float4*)(out + OFF_CO + (size_t)row * NN);
        #pragma unroll 2
        for (int i = t; i < NN / 4; i += 320) __stcs(co + i, z);
    }
}

// L6: coarse core: g_cact[a][c] = sum_{k in nbr(j_c) U {j_c}} Sc[k,c]*Tt[k,a]
__global__ void k_cact() {
    int b = blockIdx.x / ACAP, c = blockIdx.x % ACAP;
    int AC = g_acnt[b];
    if (c >= AC) return;
    int nb = b << 11;
    int j = g_aidx[b * ACAP + c];
    int rowj = nb + j;
    int cnt = g_cnt[rowj];
    size_t base = (size_t)rowj * NNZCAP;
    int t = threadIdx.x;  // 320

    __shared__ float s_w[NNZCAP];
    __shared__ int   s_kr[NNZCAP];
    __shared__ int   s_diag;
    if (t == 0) s_diag = 0;
    __syncthreads();
    for (int e = t; e < cnt; e += 320) {
        int k = g_col[base + e];
        int kr = nb + k;
        s_kr[e] = kr;
        s_w[e] = g_ScD[(size_t)kr * ACAP + c];
        if (k == j) s_diag = 1;
    }
    __syncthreads();

    if (t < AC) {
        float acc = 0.f;
        for (int e = 0; e < cnt; e++) {
            float ww = s_w[e];
            if (ww != 0.f) acc += ww * g_Tt[(size_t)s_kr[e] * ACAP + t];
        }
        if (!s_diag) {
            float ww = g_ScD[(size_t)rowj * ACAP + c];
            if (ww != 0.f) acc += ww * g_Tt[(size_t)rowj * ACAP + t];
        }
        g_cact[(size_t)b * ACAP * ACAP + (size_t)t * ACAP + c] = acc;
    }
}

// L7: active coarse rows only: zero-fill + quantized patches (~13MB).
__global__ void k_tail(float* __restrict__ out) {
    int b = blockIdx.x / ACAP, a = blockIdx.x % ACAP;
    int AC = g_acnt[b];
    if (a >= AC) return;
    int t = threadIdx.x;   // 256
    int nb = b << 11;
    int row = nb + g_aidx[b * ACAP + a];
    float4 z = make_float4(0.f, 0.f, 0.f, 0.f);
    float4* co = (float4*)(out + OFF_CO + (size_t)row * NN);
    #pragma unroll 2
    for (int i = t; i < NN / 4; i += 256) __stcs(co + i, z);
    __syncthreads();
    const float* crow = g_cact + (size_t)b * ACAP * ACAP + (size_t)a * ACAP;
    const int* ai = g_aidx + b * ACAP;
    for (int c = t; c < AC; c += 256) {
        float q = floorf(crow[c] * 10000.0f) / 10000.0f;
        out[OFF_CO + (size_t)row * NN + ai[c]] = q;
    }
}

extern "C" void kernel_launch(void* const* d_in, const int* in_sizes, int n_in,
                              void* d_out, int out_size) {
    const float* x    = (const float*)d_in[0];
    const float* adj  = (const float*)d_in[1];
    const float* W    = (const float*)d_in[2];
    const float* bptr = (const float*)d_in[3];
    float* out = (float*)d_out;

    k_head  <<<BB * NN + BB * NN / 8, 256>>>(adj, x, W);        // 1
    k_alpha <<<BB * NN / 8, 256>>>(bptr);                       // 2
    k_topk  <<<BB, 1024>>>(out, (long long)out_size);           // 3
    k_Sc    <<<BB * NN / 8, 256>>>();                           // 4 (ncu slot)
    k_Txc   <<<BB * ACAP + 3 * BB * NN, 320>>>(x, out);         // 5
    k_cact  <<<BB * ACAP, 320>>>();                             // 6
    k_tail  <<<BB * ACAP, 256>>>(out);                          // 7
}